// round 16
// baseline (speedup 1.0000x reference)
#include <cuda_runtime.h>
#include <cuda_fp16.h>
#include <math.h>
#include <stdint.h>

#define B_  2
#define T_  2048
#define C_  1024
#define H_  16
#define D_  64
#define BH_ 32
#define M_  4096
#define N3_ 3072
#define K_  1024
#define KP2_ 512      // packed k-pair words per row (K/2)

// ---------------- scratch (__device__ globals; no allocs allowed) -----------
__device__ uint32_t g_xp_h[M_*KP2_], g_xp_l[M_*KP2_];   // x packed hi/lo [m][kp]
__device__ uint32_t g_yp_h[M_*KP2_], g_yp_l[M_*KP2_];   // y packed hi/lo [m][kp]
__device__ uint32_t g_wq16[KP2_*N3_];                   // w_qkv packed [kp][n]
__device__ uint32_t g_wp16[KP2_*C_];                    // w_proj packed [kp][n]
__device__ uint32_t g_qp_h[BH_*T_*32], g_qp_l[BH_*T_*32];
__device__ uint32_t g_kp[BH_*T_*32];                    // K packed d-pairs [t][dp]
__device__ __half   g_vt[BH_*D_*T_];                    // V TRANSPOSED fp16 [d][t]
__device__ float g_cos[T_*32], g_sin[T_*32];

// ---------------- helpers ----------------------------------------------------
__device__ __forceinline__ uint32_t smem_u32(const void* p) {
    uint32_t a;
    asm("{ .reg .u64 t; cvta.to.shared.u64 t, %1; cvt.u32.u64 %0, t; }"
        : "=r"(a) : "l"(p));
    return a;
}

// pack two fp32 into f16x2 (v0 -> low half)
__device__ __forceinline__ uint32_t cvt2h(float v0, float v1) {
    uint32_t r;
    asm("cvt.rn.f16x2.f32 %0, %1, %2;" : "=r"(r) : "f"(v1), "f"(v0));
    return r;
}

// split two fp32 into f16x2 hi-pair and f16x2 lo-pair (residuals)
__device__ __forceinline__ void split2h(float v0, float v1,
                                        uint32_t& h, uint32_t& l) {
    h = cvt2h(v0, v1);
    float h0, h1;
    asm("{ .reg .f16 lo, hi; mov.b32 {lo, hi}, %2;"
        "  cvt.f32.f16 %0, lo; cvt.f32.f16 %1, hi; }"
        : "=f"(h0), "=f"(h1) : "r"(h));
    l = cvt2h(v0 - h0, v1 - h1);
}

__device__ __forceinline__ void mma_f16(float c[4], const uint32_t a[4],
                                        const uint32_t b[2]) {
    asm volatile(
        "mma.sync.aligned.m16n8k16.row.col.f32.f16.f16.f32 "
        "{%0,%1,%2,%3}, {%4,%5,%6,%7}, {%8,%9}, {%0,%1,%2,%3};"
        : "+f"(c[0]), "+f"(c[1]), "+f"(c[2]), "+f"(c[3])
        : "r"(a[0]), "r"(a[1]), "r"(a[2]), "r"(a[3]), "r"(b[0]), "r"(b[1]));
}

// warp-collective 4x m8n8 b16 matrix load from shared
__device__ __forceinline__ void ldmx4(uint32_t a, uint32_t& r0, uint32_t& r1,
                                      uint32_t& r2, uint32_t& r3) {
    asm volatile("ldmatrix.sync.aligned.m8n8.x4.shared.b16 {%0,%1,%2,%3}, [%4];"
                 : "=r"(r0), "=r"(r1), "=r"(r2), "=r"(r3) : "r"(a));
}

// fast exp2 on FMA/ALU pipes (no MUFU)
__device__ __forceinline__ float fexp2(float t) {
    t = fmaxf(t, -126.0f);
    float r = t + 12582912.0f;
    int   n = __float_as_int(r);
    float f = t - (r - 12582912.0f);
    float p = 1.33335581e-3f;
    p = fmaf(p, f, 9.61812911e-3f);
    p = fmaf(p, f, 5.55041087e-2f);
    p = fmaf(p, f, 2.40226507e-1f);
    p = fmaf(p, f, 6.93147180e-1f);
    p = fmaf(p, f, 1.0f);
    return __int_as_float(__float_as_int(p) + (n << 23));
}
#define L2E_ 1.4426950408889634f

__device__ __forceinline__ void cpa16(uint32_t s, const void* gp) {
    asm volatile("cp.async.cg.shared.global [%0], [%1], 16;" :: "r"(s), "l"(gp));
}
#define CP_COMMIT() asm volatile("cp.async.commit_group;" ::: "memory")
#define CP_WAIT1()  asm volatile("cp.async.wait_group 1;" ::: "memory")

// ---------------- RoPE table (shared fp64 pow table; fp64 sincos kept) ------
__global__ void rope_table_kernel() {
    __shared__ float sinv[32];
    const int tid = threadIdx.x;
    if (tid < 32)
        sinv[tid] = (float)pow(10000.0, -(double)(2 * tid) / 64.0);
    __syncthreads();
    int idx = blockIdx.x * 256 + tid;           // 65536
    int t = idx >> 5, i = idx & 31;
    float ff = (float)t * sinv[i];              // fp32 rounding matches ref
    double s, c;
    sincos((double)ff, &s, &c);                 // fast-math-immune reduction
    g_cos[idx] = (float)c;
    g_sin[idx] = (float)s;
}

// ---------------- converters (off the hot path) ------------------------------
__global__ __launch_bounds__(256) void convert_x_kernel(const float* __restrict__ x) {
    int i = blockIdx.x * 256 + threadIdx.x;     // over M_*K_/4 float4s
    float4 v = ((const float4*)x)[i];
    uint2 h, l;
    split2h(v.x, v.y, h.x, l.x);
    split2h(v.z, v.w, h.y, l.y);
    ((uint2*)g_xp_h)[i] = h;
    ((uint2*)g_xp_l)[i] = l;
}

// W[K][N] fp32 -> packed fp16 [kp][n] (pair k,k+1 per word; no transpose)
template <int WHICH>
__global__ __launch_bounds__(256) void convert_w_kernel(
    const float* __restrict__ W, int N)
{
    uint32_t* __restrict__ dst = WHICH ? g_wp16 : g_wq16;   // device-side symbol!
    int i = blockIdx.x * 256 + threadIdx.x;     // over (K_/2)*N/4 quads
    int kp  = i / (N >> 2);
    int nc4 = (i - kp * (N >> 2)) << 2;
    float4 a = *(const float4*)(W + (size_t)(2 * kp)     * N + nc4);
    float4 b = *(const float4*)(W + (size_t)(2 * kp + 1) * N + nc4);
    uint4 o;
    o.x = cvt2h(a.x, b.x);
    o.y = cvt2h(a.y, b.y);
    o.z = cvt2h(a.z, b.z);
    o.w = cvt2h(a.w, b.w);
    ((uint4*)dst)[i] = o;
}

// ---------------- fp16 2-pass GEMM: ldmatrix A frags, packed B --------------
#define APSTR 20                      // packed A row stride (16 data + 4 pad)
#define AP_W (128 * APSTR)            // 2560 words per A array
#define BPSTR 136                     // packed B row stride (frag banks 8tq+g)
#define BP_W (16 * BPSTR)             // 2176 words
#define STG_W (2 * AP_W + BP_W)       // 7296 words / stage
#define GEMM_SMEM_BYTES (2 * STG_W * 4)  // 58,368 B

__device__ __forceinline__ void gemm_load_stage(
    uint32_t su, const uint32_t* __restrict__ Aph, const uint32_t* __restrict__ Apl,
    const uint32_t* __restrict__ Wp, int m0, int n0, int jc, int N, int tid)
{
    // A hi/lo: 128 rows x 16 pair-words = 512 quads each
    #pragma unroll
    for (int i = 0; i < 2; i++) {
        int q = i * 256 + tid;
        int row = q >> 2, ch = (q & 3) * 4;
        const size_t ga = (size_t)(m0 + row) * KP2_ + jc * 16 + ch;
        cpa16(su + (row * APSTR + ch) * 4,            Aph + ga);
        cpa16(su + (AP_W + row * APSTR + ch) * 4,     Apl + ga);
    }
    // B packed: 16 kp rows x 128 n words = 512 quads
    const uint32_t bu = su + 2 * AP_W * 4;
    #pragma unroll
    for (int i = 0; i < 2; i++) {
        int q = i * 256 + tid;
        int row = q >> 5, ch = (q & 31) * 4;
        cpa16(bu + (row * BPSTR + ch) * 4,
              Wp + (size_t)(jc * 16 + row) * N + n0 + ch);
    }
}

template <int MODE>
__global__ __launch_bounds__(256, 2) void gemm_f16(
    const float* __restrict__ bias, float* __restrict__ out)
{
    const int N = MODE ? C_ : N3_;
    extern __shared__ uint32_t dsm[];
    const uint32_t sb = smem_u32(dsm);

    // device-side symbols (host-side would give host shadow addresses)
    const uint32_t* Aph = MODE ? g_yp_h : g_xp_h;
    const uint32_t* Apl = MODE ? g_yp_l : g_xp_l;
    const uint32_t* Wp  = MODE ? g_wp16 : g_wq16;

    const int tid  = threadIdx.x;
    const int wid  = tid >> 5;
    const int lane = tid & 31;
    const int g  = lane >> 2;
    const int tq = lane & 3;
    const int wm = wid >> 2;
    const int wn = wid & 3;
    const int m0 = blockIdx.y * 128;
    const int n0 = blockIdx.x * 128;

    // ldmatrix lane geometry (A operand, m16k16 per x4)
    const int arow  = (lane & 7) + ((lane >> 3) & 1) * 8;
    const int acolw = (lane >> 4) * 4;

    float acc[4][4][4] = {};

    gemm_load_stage(sb, Aph, Apl, Wp, m0, n0, 0, N, tid);
    CP_COMMIT();

    for (int jc = 0; jc < K_ / 32; jc++) {
        const int s = jc & 1;
        if (jc + 1 < K_ / 32)
            gemm_load_stage(sb + (uint32_t)(s ^ 1) * STG_W * 4, Aph, Apl, Wp,
                            m0, n0, jc + 1, N, tid);
        CP_COMMIT();
        CP_WAIT1();
        __syncthreads();

        const uint32_t stg_b = sb + (uint32_t)s * STG_W * 4;
        const uint32_t* Bp = dsm + s * STG_W + 2 * AP_W;

        #pragma unroll
        for (int ks = 0; ks < 2; ks++) {
            const int cp = 8 * ks + tq;
            uint32_t ah[4][4], al[4][4], bh[4][2];
            #pragma unroll
            for (int mi = 0; mi < 4; mi++) {
                uint32_t ad = stg_b +
                    (((wm * 64 + mi * 16 + arow) * APSTR) + ks * 8 + acolw) * 4;
                ldmx4(ad, ah[mi][0], ah[mi][1], ah[mi][2], ah[mi][3]);
                ldmx4(ad + AP_W * 4, al[mi][0], al[mi][1], al[mi][2], al[mi][3]);
            }
            #pragma unroll
            for (int ni = 0; ni < 4; ni++) {
                int nb = wn * 32 + ni * 8 + g;
                bh[ni][0] = Bp[cp * BPSTR + nb];
                bh[ni][1] = Bp[(cp + 4) * BPSTR + nb];
            }
            #pragma unroll
            for (int mi = 0; mi < 4; mi++)
                #pragma unroll
                for (int ni = 0; ni < 4; ni++) {
                    mma_f16(acc[mi][ni], ah[mi], bh[ni]);
                    mma_f16(acc[mi][ni], al[mi], bh[ni]);
                }
        }
        __syncthreads();
    }

    // ------------- epilogue -------------
    #pragma unroll
    for (int mi = 0; mi < 4; mi++) {
        #pragma unroll
        for (int ni = 0; ni < 4; ni++) {
            const float* c = acc[mi][ni];
            int r0 = m0 + wm * 64 + mi * 16 + g;
            int nc = n0 + wn * 32 + ni * 8 + 2 * tq;
            #pragma unroll
            for (int half = 0; half < 2; half++) {
                int m = r0 + half * 8;
                float e = c[half * 2 + 0];
                float o = c[half * 2 + 1];
                if (MODE == 0) {
                    int b = m >> 11, t = m & 2047;
                    int sec = nc >> 10, cc = nc & 1023;
                    int hd = cc >> 6, d = cc & 63;       // d even
                    if (sec == 2) {
                        size_t vb = ((size_t)((b << 4) + hd) * D_ + d) * T_ + t;
                        g_vt[vb]      = __float2half(e);
                        g_vt[vb + T_] = __float2half(o);
                    } else {
                        size_t idx = ((size_t)((b << 4) + hd) * T_ + t) * 32 + (d >> 1);
                        float co = g_cos[t * 32 + (d >> 1)];
                        float si = g_sin[t * 32 + (d >> 1)];
                        float oe = e * co - o * si;
                        float oo = e * si + o * co;
                        if (sec == 0) {
                            uint32_t ph, pl;
                            split2h(oe * 0.125f, oo * 0.125f, ph, pl);
                            g_qp_h[idx] = ph; g_qp_l[idx] = pl;
                        } else {
                            g_kp[idx] = cvt2h(oe, oo);
                        }
                    }
                } else {
                    float2 bv = *(const float2*)(bias + nc);
                    *(float2*)(out + (size_t)m * C_ + nc) =
                        make_float2(e + bv.x, o + bv.y);
                }
            }
        }
    }
}

// ---------------- MMA flash attention (fp16; ldmatrix K/V frags) ------------
#define KPSTR 36
#define KPW   (64 * KPSTR)                 // 2304 words (K tile)
#define VSTR  36
#define VT_W  (64 * VSTR)                  // 2304 words (V tile, [d][kvpair])
#define ASTG_W (KPW + VT_W)                // 4608 words per stage
#define ATTN_WORDS (2 * ASTG_W)            // 9216
#define ATTN_SMEM_B (ATTN_WORDS * 4)       // 36,864 B

__device__ __forceinline__ void attn_load_stage(
    uint32_t su, const uint32_t* __restrict__ kp,
    const __half* __restrict__ vt, int kv0, int tid)
{
    #pragma unroll
    for (int i = 0; i < 2; i++) {    // K: 64 kv rows x 32 words (d-pairs)
        int c = i * 256 + tid;
        int r = c >> 3, ch = (c & 7) * 4;
        cpa16(su + (r * KPSTR + ch) * 4, kp + (size_t)(kv0 + r) * 32 + ch);
    }
    #pragma unroll
    for (int i = 0; i < 2; i++) {    // V^T: 64 d rows x 64 halves (32 words)
        int c = i * 256 + tid;
        int r = c >> 3, ch = c & 7;
        cpa16(su + (KPW + r * VSTR + ch * 4) * 4,
              vt + (size_t)r * T_ + kv0 + ch * 8);
    }
}

__global__ __launch_bounds__(256, 2) void attn_mma() {
    extern __shared__ uint32_t sw[];
    const uint32_t sb = smem_u32(sw);
    const int tid  = threadIdx.x;
    const int wid  = tid >> 5, lane = tid & 31;
    const int g    = lane >> 2, tq = lane & 3;
    const int qt   = (int)gridDim.x - 1 - (int)blockIdx.x;  // heavy-first
    const int bh   = blockIdx.y;
    const int q0   = qt * 128;

    const uint32_t* kp = g_kp + (size_t)bh * T_ * 32;
    const __half*   vt = g_vt + (size_t)bh * D_ * T_;

    // ldmatrix lane geometry (B operand, two n8 tiles per x4)
    const int krow  = ((lane >> 4) * 8) + (lane & 7);
    const int kcolw = ((lane >> 3) & 1) * 4;

    // ---- Q fragments straight from packed gmem ----
    const int wrow0 = q0 + wid * 16;
    uint32_t qh[4][4], ql[4][4];
    {
        const size_t r0 = ((size_t)bh * T_ + wrow0 + g) * 32;
        const size_t r8 = r0 + 8 * 32;
        #pragma unroll
        for (int ks = 0; ks < 4; ks++) {
            int cp0 = 8 * ks + tq;
            qh[ks][0] = g_qp_h[r0 + cp0];     ql[ks][0] = g_qp_l[r0 + cp0];
            qh[ks][1] = g_qp_h[r8 + cp0];     ql[ks][1] = g_qp_l[r8 + cp0];
            qh[ks][2] = g_qp_h[r0 + cp0 + 4]; ql[ks][2] = g_qp_l[r0 + cp0 + 4];
            qh[ks][3] = g_qp_h[r8 + cp0 + 4]; ql[ks][3] = g_qp_l[r8 + cp0 + 4];
        }
    }

    float accO[8][4] = {};
    float mrow[2] = {-1e30f, -1e30f};
    float lrow[2] = {0.0f, 0.0f};
    const int nkv = 2 * qt + 2;

    attn_load_stage(sb, kp, vt, 0, tid);  CP_COMMIT();
    if (nkv > 1) attn_load_stage(sb + ASTG_W * 4, kp, vt, 64, tid);
    CP_COMMIT();

    for (int j = 0; j < nkv; j++) {
        const int s = j & 1;
        const int kv0 = j * 64;
        const uint32_t Kb = sb + (uint32_t)s * ASTG_W * 4;
        const uint32_t Vb = Kb + KPW * 4;

        CP_WAIT1();
        __syncthreads();

        if (kv0 <= wrow0 + 15) {
            // ---- S = Q @ K^T (2-pass; K frags via ldmatrix.x4) ----
            float accS[8][4] = {};
            #pragma unroll
            for (int ks = 0; ks < 4; ks++) {
                #pragma unroll
                for (int np = 0; np < 4; np++) {
                    uint32_t b0[2], b1[2];
                    ldmx4(Kb + (((np * 16 + krow) * KPSTR) + ks * 8 + kcolw) * 4,
                          b0[0], b0[1], b1[0], b1[1]);
                    mma_f16(accS[2*np],   qh[ks], b0);
                    mma_f16(accS[2*np],   ql[ks], b0);
                    mma_f16(accS[2*np+1], qh[ks], b1);
                    mma_f16(accS[2*np+1], ql[ks], b1);
                }
            }

            // ---- causal mask ----
            if (kv0 + 63 > wrow0) {
                #pragma unroll
                for (int nf = 0; nf < 8; nf++)
                    #pragma unroll
                    for (int r = 0; r < 4; r++) {
                        int row = wrow0 + g + (r >> 1) * 8;
                        int col = kv0 + nf * 8 + 2 * tq + (r & 1);
                        if (col > row) accS[nf][r] = -1e30f;
                    }
            }

            // ---- online softmax (fexp2, no MUFU) ----
            #pragma unroll
            for (int hh = 0; hh < 2; hh++) {
                float mx = -1e30f;
                #pragma unroll
                for (int nf = 0; nf < 8; nf++)
                    mx = fmaxf(mx, fmaxf(accS[nf][2*hh], accS[nf][2*hh+1]));
                mx = fmaxf(mx, __shfl_xor_sync(0xffffffffu, mx, 1));
                mx = fmaxf(mx, __shfl_xor_sync(0xffffffffu, mx, 2));
                float mn = fmaxf(mrow[hh], mx);
                float corr = fexp2((mrow[hh] - mn) * L2E_);
                mrow[hh] = mn;
                float mnL = mn * L2E_;
                float ps = 0.0f;
                #pragma unroll
                for (int nf = 0; nf < 8; nf++) {
                    float p0 = fexp2(fmaf(accS[nf][2*hh],   L2E_, -mnL));
                    float p1 = fexp2(fmaf(accS[nf][2*hh+1], L2E_, -mnL));
                    accS[nf][2*hh] = p0; accS[nf][2*hh+1] = p1;
                    ps += p0 + p1;
                }
                ps += __shfl_xor_sync(0xffffffffu, ps, 1);
                ps += __shfl_xor_sync(0xffffffffu, ps, 2);
                lrow[hh] = lrow[hh] * corr + ps;
                #pragma unroll
                for (int nf = 0; nf < 8; nf++) {
                    accO[nf][2*hh]   *= corr;
                    accO[nf][2*hh+1] *= corr;
                }
            }

            // ---- O += P @ V (P single-pass fp16; V frags via ldmatrix.x4) ----
            #pragma unroll
            for (int ks = 0; ks < 4; ks++) {
                uint32_t ph[4];
                ph[0] = cvt2h(accS[2*ks][0],   accS[2*ks][1]);
                ph[1] = cvt2h(accS[2*ks][2],   accS[2*ks][3]);
                ph[2] = cvt2h(accS[2*ks+1][0], accS[2*ks+1][1]);
                ph[3] = cvt2h(accS[2*ks+1][2], accS[2*ks+1][3]);
                #pragma unroll
                for (int np = 0; np < 4; np++) {
                    uint32_t v0[2], v1[2];
                    ldmx4(Vb + (((np * 16 + krow) * VSTR) + ks * 8 + kcolw) * 4,
                          v0[0], v0[1], v1[0], v1[1]);
                    mma_f16(accO[2*np],   ph, v0);
                    mma_f16(accO[2*np+1], ph, v1);
                }
            }
        }
        __syncthreads();   // all reads of stage s done before refill

        if (j + 2 < nkv)
            attn_load_stage(sb + (uint32_t)s * ASTG_W * 4, kp, vt, kv0 + 128, tid);
        CP_COMMIT();
    }

    // ---- write y packed hi/lo [m][kp] (proj A-operand, zero-cvt there) ----
    const int b = bh >> 4, hd = bh & 15;
    #pragma unroll
    for (int hh = 0; hh < 2; hh++) {
        float inv = 1.0f / lrow[hh];
        int t = q0 + wid * 16 + g + hh * 8;
        size_t rowbase = (size_t)(b * T_ + t) * KP2_ + hd * 32;
        #pragma unroll
        for (int nf = 0; nf < 8; nf++) {
            uint32_t ph, pl;
            split2h(accO[nf][2*hh] * inv, accO[nf][2*hh+1] * inv, ph, pl);
            g_yp_h[rowbase + nf * 4 + tq] = ph;
            g_yp_l[rowbase + nf * 4 + tq] = pl;
        }
    }
}

// ---------------------------------------------------------------------------
extern "C" void kernel_launch(void* const* d_in, const int* in_sizes, int n_in,
                              void* d_out, int out_size)
{
    const float* x      = (const float*)d_in[0];
    const float* w_qkv  = (const float*)d_in[1];
    const float* w_proj = (const float*)d_in[2];
    const float* b_proj = (const float*)d_in[3];
    float* out = (float*)d_out;
    (void)in_sizes; (void)n_in; (void)out_size;

    cudaFuncSetAttribute(gemm_f16<0>,
                         cudaFuncAttributeMaxDynamicSharedMemorySize, GEMM_SMEM_BYTES);
    cudaFuncSetAttribute(gemm_f16<1>,
                         cudaFuncAttributeMaxDynamicSharedMemorySize, GEMM_SMEM_BYTES);
    cudaFuncSetAttribute(attn_mma,
                         cudaFuncAttributeMaxDynamicSharedMemorySize, ATTN_SMEM_B);

    rope_table_kernel<<<256, 256>>>();
    convert_x_kernel<<<M_ * K_ / 4 / 256, 256>>>(x);
    convert_w_kernel<0><<<(KP2_ * N3_ / 4) / 256, 256>>>(w_qkv, N3_);
    convert_w_kernel<1><<<(KP2_ * C_  / 4) / 256, 256>>>(w_proj, C_);
    gemm_f16<0><<<dim3(N3_ / 128, M_ / 128), 256, GEMM_SMEM_BYTES>>>(nullptr, nullptr);
    attn_mma<<<dim3(T_ / 128, BH_), 256, ATTN_SMEM_B>>>();
    gemm_f16<1><<<dim3(C_ / 128, M_ / 128), 256, GEMM_SMEM_BYTES>>>(b_proj, out);
}

// round 17
// speedup vs baseline: 1.0214x; 1.0214x over previous
#include <cuda_runtime.h>
#include <cuda_fp16.h>
#include <math.h>
#include <stdint.h>

#define B_  2
#define T_  2048
#define C_  1024
#define H_  16
#define D_  64
#define BH_ 32
#define M_  4096
#define N3_ 3072
#define K_  1024
#define KP2_ 512      // packed k-pair words per row (K/2)

// ---------------- scratch (__device__ globals; no allocs allowed) -----------
__device__ uint32_t g_xp_h[M_*KP2_], g_xp_l[M_*KP2_];   // x packed hi/lo [m][kp]
__device__ uint32_t g_yp_h[M_*KP2_], g_yp_l[M_*KP2_];   // y packed hi/lo [m][kp]
__device__ uint32_t g_wq16[KP2_*N3_];                   // w_qkv packed [kp][n]
__device__ uint32_t g_wp16[KP2_*C_];                    // w_proj packed [kp][n]
__device__ uint32_t g_qp_h[BH_*T_*32], g_qp_l[BH_*T_*32];
__device__ uint32_t g_kp[BH_*T_*32];                    // K packed d-pairs [t][dp]
__device__ __half   g_vt[BH_*D_*T_];                    // V TRANSPOSED fp16 [d][t]
__device__ float g_cos[T_*32], g_sin[T_*32];

// ---------------- helpers ----------------------------------------------------
__device__ __forceinline__ uint32_t smem_u32(const void* p) {
    uint32_t a;
    asm("{ .reg .u64 t; cvta.to.shared.u64 t, %1; cvt.u32.u64 %0, t; }"
        : "=r"(a) : "l"(p));
    return a;
}

__device__ __forceinline__ uint32_t cvt2h(float v0, float v1) {
    uint32_t r;
    asm("cvt.rn.f16x2.f32 %0, %1, %2;" : "=r"(r) : "f"(v1), "f"(v0));
    return r;
}

__device__ __forceinline__ void split2h(float v0, float v1,
                                        uint32_t& h, uint32_t& l) {
    h = cvt2h(v0, v1);
    float h0, h1;
    asm("{ .reg .f16 lo, hi; mov.b32 {lo, hi}, %2;"
        "  cvt.f32.f16 %0, lo; cvt.f32.f16 %1, hi; }"
        : "=f"(h0), "=f"(h1) : "r"(h));
    l = cvt2h(v0 - h0, v1 - h1);
}

__device__ __forceinline__ void mma_f16(float c[4], const uint32_t a[4],
                                        const uint32_t b[2]) {
    asm volatile(
        "mma.sync.aligned.m16n8k16.row.col.f32.f16.f16.f32 "
        "{%0,%1,%2,%3}, {%4,%5,%6,%7}, {%8,%9}, {%0,%1,%2,%3};"
        : "+f"(c[0]), "+f"(c[1]), "+f"(c[2]), "+f"(c[3])
        : "r"(a[0]), "r"(a[1]), "r"(a[2]), "r"(a[3]), "r"(b[0]), "r"(b[1]));
}

// fast exp2 on FMA/ALU pipes (no MUFU)
__device__ __forceinline__ float fexp2(float t) {
    t = fmaxf(t, -126.0f);
    float r = t + 12582912.0f;
    int   n = __float_as_int(r);
    float f = t - (r - 12582912.0f);
    float p = 1.33335581e-3f;
    p = fmaf(p, f, 9.61812911e-3f);
    p = fmaf(p, f, 5.55041087e-2f);
    p = fmaf(p, f, 2.40226507e-1f);
    p = fmaf(p, f, 6.93147180e-1f);
    p = fmaf(p, f, 1.0f);
    return __int_as_float(__float_as_int(p) + (n << 23));
}
#define L2E_ 1.4426950408889634f

__device__ __forceinline__ void cpa16(uint32_t s, const void* gp) {
    asm volatile("cp.async.cg.shared.global [%0], [%1], 16;" :: "r"(s), "l"(gp));
}
#define CP_COMMIT() asm volatile("cp.async.commit_group;" ::: "memory")
#define CP_WAIT1()  asm volatile("cp.async.wait_group 1;" ::: "memory")

// ---------------- RoPE table (shared fp64 pow table; fp64 sincos kept) ------
__global__ void rope_table_kernel() {
    __shared__ float sinv[32];
    const int tid = threadIdx.x;
    if (tid < 32)
        sinv[tid] = (float)pow(10000.0, -(double)(2 * tid) / 64.0);
    __syncthreads();
    int idx = blockIdx.x * 256 + tid;           // 65536
    int t = idx >> 5, i = idx & 31;
    float ff = (float)t * sinv[i];              // fp32 rounding matches ref
    double s, c;
    sincos((double)ff, &s, &c);                 // fast-math-immune reduction
    g_cos[idx] = (float)c;
    g_sin[idx] = (float)s;
}

// ---------------- converters (off the hot path) ------------------------------
__global__ __launch_bounds__(256) void convert_x_kernel(const float* __restrict__ x) {
    int i = blockIdx.x * 256 + threadIdx.x;     // over M_*K_/4 float4s
    float4 v = ((const float4*)x)[i];
    uint2 h, l;
    split2h(v.x, v.y, h.x, l.x);
    split2h(v.z, v.w, h.y, l.y);
    ((uint2*)g_xp_h)[i] = h;
    ((uint2*)g_xp_l)[i] = l;
}

// W[K][N] fp32 -> packed fp16 [kp][n] (pair k,k+1 per word; no transpose)
template <int WHICH>
__global__ __launch_bounds__(256) void convert_w_kernel(
    const float* __restrict__ W, int N)
{
    uint32_t* __restrict__ dst = WHICH ? g_wp16 : g_wq16;   // device-side symbol!
    int i = blockIdx.x * 256 + threadIdx.x;     // over (K_/2)*N/4 quads
    int kp  = i / (N >> 2);
    int nc4 = (i - kp * (N >> 2)) << 2;
    float4 a = *(const float4*)(W + (size_t)(2 * kp)     * N + nc4);
    float4 b = *(const float4*)(W + (size_t)(2 * kp + 1) * N + nc4);
    uint4 o;
    o.x = cvt2h(a.x, b.x);
    o.y = cvt2h(a.y, b.y);
    o.z = cvt2h(a.z, b.z);
    o.w = cvt2h(a.w, b.w);
    ((uint4*)dst)[i] = o;
}

// ---------------- fp16 2-pass GEMM: 3-stage ring, ONE sync per chunk --------
#define APSTR 20                      // packed A row stride (16 data + 4 pad)
#define AP_W (128 * APSTR)            // 2560 words per A array
#define BPSTR 136                     // packed B row stride (frag banks 8tq+g)
#define BP_W (16 * BPSTR)             // 2176 words
#define STG_W (2 * AP_W + BP_W)       // 7296 words / stage
#define GEMM_SMEM_BYTES (3 * STG_W * 4)  // 87,552 B
#define NCH (K_ / 32)                 // 32 chunks

__device__ __forceinline__ void gemm_load_stage(
    uint32_t su, const uint32_t* __restrict__ Aph, const uint32_t* __restrict__ Apl,
    const uint32_t* __restrict__ Wp, int m0, int n0, int jc, int N, int tid)
{
    #pragma unroll
    for (int i = 0; i < 2; i++) {
        int q = i * 256 + tid;
        int row = q >> 2, ch = (q & 3) * 4;
        const size_t ga = (size_t)(m0 + row) * KP2_ + jc * 16 + ch;
        cpa16(su + (row * APSTR + ch) * 4,            Aph + ga);
        cpa16(su + (AP_W + row * APSTR + ch) * 4,     Apl + ga);
    }
    const uint32_t bu = su + 2 * AP_W * 4;
    #pragma unroll
    for (int i = 0; i < 2; i++) {
        int q = i * 256 + tid;
        int row = q >> 5, ch = (q & 31) * 4;
        cpa16(bu + (row * BPSTR + ch) * 4,
              Wp + (size_t)(jc * 16 + row) * N + n0 + ch);
    }
}

template <int MODE>
__global__ __launch_bounds__(256, 2) void gemm_f16(
    const float* __restrict__ bias, float* __restrict__ out)
{
    const int N = MODE ? C_ : N3_;
    extern __shared__ uint32_t dsm[];
    const uint32_t sb = smem_u32(dsm);

    // device-side symbols (host-side would give host shadow addresses)
    const uint32_t* Aph = MODE ? g_yp_h : g_xp_h;
    const uint32_t* Apl = MODE ? g_yp_l : g_xp_l;
    const uint32_t* Wp  = MODE ? g_wp16 : g_wq16;

    const int tid  = threadIdx.x;
    const int wid  = tid >> 5;
    const int lane = tid & 31;
    const int g  = lane >> 2;
    const int tq = lane & 3;
    const int wm = wid >> 2;
    const int wn = wid & 3;
    const int m0 = blockIdx.y * 128;
    const int n0 = blockIdx.x * 128;

    float acc[4][4][4] = {};

    gemm_load_stage(sb, Aph, Apl, Wp, m0, n0, 0, N, tid);  CP_COMMIT();
    gemm_load_stage(sb + STG_W * 4, Aph, Apl, Wp, m0, n0, 1, N, tid);  CP_COMMIT();

    for (int jc = 0; jc < NCH; jc++) {
        CP_WAIT1();
        __syncthreads();      // chunk jc visible to all; all finished jc-1
        if (jc + 2 < NCH)     // refill buffer (jc+2)%3 == (jc-1)%3: safe
            gemm_load_stage(sb + (uint32_t)((jc + 2) % 3) * STG_W * 4,
                            Aph, Apl, Wp, m0, n0, jc + 2, N, tid);
        CP_COMMIT();

        const uint32_t* Ah = dsm + (jc % 3) * STG_W;
        const uint32_t* Al = Ah + AP_W;
        const uint32_t* Bp = Ah + 2 * AP_W;

        #pragma unroll
        for (int ks = 0; ks < 2; ks++) {
            const int cp = 8 * ks + tq;
            uint32_t ah[4][4], al[4][4], bh[4][2];
            #pragma unroll
            for (int mi = 0; mi < 4; mi++) {
                int mb = wm * 64 + mi * 16 + g;
                ah[mi][0] = Ah[mb * APSTR + cp];
                ah[mi][1] = Ah[(mb + 8) * APSTR + cp];
                ah[mi][2] = Ah[mb * APSTR + cp + 4];
                ah[mi][3] = Ah[(mb + 8) * APSTR + cp + 4];
                al[mi][0] = Al[mb * APSTR + cp];
                al[mi][1] = Al[(mb + 8) * APSTR + cp];
                al[mi][2] = Al[mb * APSTR + cp + 4];
                al[mi][3] = Al[(mb + 8) * APSTR + cp + 4];
            }
            #pragma unroll
            for (int ni = 0; ni < 4; ni++) {
                int nb = wn * 32 + ni * 8 + g;
                bh[ni][0] = Bp[cp * BPSTR + nb];
                bh[ni][1] = Bp[(cp + 4) * BPSTR + nb];
            }
            #pragma unroll
            for (int mi = 0; mi < 4; mi++)
                #pragma unroll
                for (int ni = 0; ni < 4; ni++) {
                    mma_f16(acc[mi][ni], ah[mi], bh[ni]);
                    mma_f16(acc[mi][ni], al[mi], bh[ni]);
                }
        }
    }

    // ------------- epilogue -------------
    #pragma unroll
    for (int mi = 0; mi < 4; mi++) {
        #pragma unroll
        for (int ni = 0; ni < 4; ni++) {
            const float* c = acc[mi][ni];
            int r0 = m0 + wm * 64 + mi * 16 + g;
            int nc = n0 + wn * 32 + ni * 8 + 2 * tq;
            #pragma unroll
            for (int half = 0; half < 2; half++) {
                int m = r0 + half * 8;
                float e = c[half * 2 + 0];
                float o = c[half * 2 + 1];
                if (MODE == 0) {
                    int b = m >> 11, t = m & 2047;
                    int sec = nc >> 10, cc = nc & 1023;
                    int hd = cc >> 6, d = cc & 63;       // d even
                    if (sec == 2) {
                        size_t vb = ((size_t)((b << 4) + hd) * D_ + d) * T_ + t;
                        g_vt[vb]      = __float2half(e);
                        g_vt[vb + T_] = __float2half(o);
                    } else {
                        size_t idx = ((size_t)((b << 4) + hd) * T_ + t) * 32 + (d >> 1);
                        float co = g_cos[t * 32 + (d >> 1)];
                        float si = g_sin[t * 32 + (d >> 1)];
                        float oe = e * co - o * si;
                        float oo = e * si + o * co;
                        if (sec == 0) {
                            uint32_t ph, pl;
                            split2h(oe * 0.125f, oo * 0.125f, ph, pl);
                            g_qp_h[idx] = ph; g_qp_l[idx] = pl;
                        } else {
                            g_kp[idx] = cvt2h(oe, oo);
                        }
                    }
                } else {
                    float2 bv = *(const float2*)(bias + nc);
                    *(float2*)(out + (size_t)m * C_ + nc) =
                        make_float2(e + bv.x, o + bv.y);
                }
            }
        }
    }
}

// ---------------- MMA flash attention: 64q x 128thr, 3-stage, 1 sync/tile ---
#define KPSTR 36
#define KPW   (64 * KPSTR)                 // 2304 words (K tile)
#define VSTR  36
#define VT_W  (64 * VSTR)                  // 2304 words (V tile, [d][kvpair])
#define ASTG_W (KPW + VT_W)                // 4608 words per stage
#define ATTN_WORDS (3 * ASTG_W)            // 13824
#define ATTN_SMEM_B (ATTN_WORDS * 4)       // 55,296 B

__device__ __forceinline__ void attn_load_stage(
    uint32_t su, const uint32_t* __restrict__ kp,
    const __half* __restrict__ vt, int kv0, int tid)
{
    #pragma unroll
    for (int i = 0; i < 4; i++) {    // K: 64 kv rows x 32 words (512 quads)
        int c = i * 128 + tid;
        int r = c >> 3, ch = (c & 7) * 4;
        cpa16(su + (r * KPSTR + ch) * 4, kp + (size_t)(kv0 + r) * 32 + ch);
    }
    #pragma unroll
    for (int i = 0; i < 4; i++) {    // V^T: 64 d rows x 64 halves (512 quads)
        int c = i * 128 + tid;
        int r = c >> 3, ch = c & 7;
        cpa16(su + (KPW + r * VSTR + ch * 4) * 4,
              vt + (size_t)r * T_ + kv0 + ch * 8);
    }
}

__global__ __launch_bounds__(128, 4) void attn_mma() {
    extern __shared__ uint32_t sw[];
    const uint32_t sb = smem_u32(sw);
    const int tid  = threadIdx.x;
    const int wid  = tid >> 5, lane = tid & 31;
    const int g    = lane >> 2, tq = lane & 3;
    const int qt   = (int)gridDim.x - 1 - (int)blockIdx.x;  // heavy-first
    const int bh   = blockIdx.y;
    const int q0   = qt * 64;

    const uint32_t* kp = g_kp + (size_t)bh * T_ * 32;
    const __half*   vt = g_vt + (size_t)bh * D_ * T_;

    // ---- Q fragments straight from packed gmem ----
    const int wrow0 = q0 + wid * 16;
    uint32_t qh[4][4], ql[4][4];
    {
        const size_t r0 = ((size_t)bh * T_ + wrow0 + g) * 32;
        const size_t r8 = r0 + 8 * 32;
        #pragma unroll
        for (int ks = 0; ks < 4; ks++) {
            int cp0 = 8 * ks + tq;
            qh[ks][0] = g_qp_h[r0 + cp0];     ql[ks][0] = g_qp_l[r0 + cp0];
            qh[ks][1] = g_qp_h[r8 + cp0];     ql[ks][1] = g_qp_l[r8 + cp0];
            qh[ks][2] = g_qp_h[r0 + cp0 + 4]; ql[ks][2] = g_qp_l[r0 + cp0 + 4];
            qh[ks][3] = g_qp_h[r8 + cp0 + 4]; ql[ks][3] = g_qp_l[r8 + cp0 + 4];
        }
    }

    float accO[8][4] = {};
    float mrow[2] = {-1e30f, -1e30f};
    float lrow[2] = {0.0f, 0.0f};
    const int nkv = qt + 1;      // 64-kv tiles covering rows q0..q0+63

    attn_load_stage(sb, kp, vt, 0, tid);  CP_COMMIT();
    if (nkv > 1) attn_load_stage(sb + ASTG_W * 4, kp, vt, 64, tid);
    CP_COMMIT();

    for (int j = 0; j < nkv; j++) {
        const int kv0 = j * 64;

        CP_WAIT1();
        __syncthreads();      // tile j visible; all warps finished tile j-1
        if (j + 2 < nkv)      // refill buffer (j+2)%3 == (j-1)%3: safe
            attn_load_stage(sb + (uint32_t)((j + 2) % 3) * ASTG_W * 4,
                            kp, vt, kv0 + 128, tid);
        CP_COMMIT();

        const uint32_t* Kh = sw + (j % 3) * ASTG_W;
        const uint32_t* Vs = Kh + KPW;

        // ---- S = Q @ K^T (2-pass: qh*K + ql*K) ----
        float accS[8][4] = {};
        #pragma unroll
        for (int ks = 0; ks < 4; ks++) {
            const int cp = 8 * ks + tq;
            #pragma unroll
            for (int nf = 0; nf < 8; nf++) {
                const int nb = nf * 8 + g;
                uint32_t kh[2];
                kh[0] = Kh[nb * KPSTR + cp];
                kh[1] = Kh[nb * KPSTR + cp + 4];
                mma_f16(accS[nf], qh[ks], kh);
                mma_f16(accS[nf], ql[ks], kh);
            }
        }

        // ---- causal mask (only the final tile can clip this warp) ----
        if (kv0 + 63 > wrow0) {
            #pragma unroll
            for (int nf = 0; nf < 8; nf++)
                #pragma unroll
                for (int r = 0; r < 4; r++) {
                    int row = wrow0 + g + (r >> 1) * 8;
                    int col = kv0 + nf * 8 + 2 * tq + (r & 1);
                    if (col > row) accS[nf][r] = -1e30f;
                }
        }

        // ---- online softmax (fexp2, no MUFU) ----
        #pragma unroll
        for (int hh = 0; hh < 2; hh++) {
            float mx = -1e30f;
            #pragma unroll
            for (int nf = 0; nf < 8; nf++)
                mx = fmaxf(mx, fmaxf(accS[nf][2*hh], accS[nf][2*hh+1]));
            mx = fmaxf(mx, __shfl_xor_sync(0xffffffffu, mx, 1));
            mx = fmaxf(mx, __shfl_xor_sync(0xffffffffu, mx, 2));
            float mn = fmaxf(mrow[hh], mx);
            float corr = fexp2((mrow[hh] - mn) * L2E_);
            mrow[hh] = mn;
            float mnL = mn * L2E_;
            float ps = 0.0f;
            #pragma unroll
            for (int nf = 0; nf < 8; nf++) {
                float p0 = fexp2(fmaf(accS[nf][2*hh],   L2E_, -mnL));
                float p1 = fexp2(fmaf(accS[nf][2*hh+1], L2E_, -mnL));
                accS[nf][2*hh] = p0; accS[nf][2*hh+1] = p1;
                ps += p0 + p1;
            }
            ps += __shfl_xor_sync(0xffffffffu, ps, 1);
            ps += __shfl_xor_sync(0xffffffffu, ps, 2);
            lrow[hh] = lrow[hh] * corr + ps;
            #pragma unroll
            for (int nf = 0; nf < 8; nf++) {
                accO[nf][2*hh]   *= corr;
                accO[nf][2*hh+1] *= corr;
            }
        }

        // ---- O += P @ V (P single-pass fp16; frags from accS regs) ----
        #pragma unroll
        for (int ks = 0; ks < 4; ks++) {
            uint32_t ph[4];
            ph[0] = cvt2h(accS[2*ks][0],   accS[2*ks][1]);
            ph[1] = cvt2h(accS[2*ks][2],   accS[2*ks][3]);
            ph[2] = cvt2h(accS[2*ks+1][0], accS[2*ks+1][1]);
            ph[3] = cvt2h(accS[2*ks+1][2], accS[2*ks+1][3]);
            const int cp = 8 * ks + tq;
            #pragma unroll
            for (int nf = 0; nf < 8; nf++) {
                const int nb = nf * 8 + g;
                uint32_t vh[2];
                vh[0] = Vs[nb * VSTR + cp];
                vh[1] = Vs[nb * VSTR + cp + 4];
                mma_f16(accO[nf], ph, vh);
            }
        }
    }

    // ---- write y packed hi/lo [m][kp] (proj A-operand, zero-cvt there) ----
    const int b = bh >> 4, hd = bh & 15;
    #pragma unroll
    for (int hh = 0; hh < 2; hh++) {
        float inv = 1.0f / lrow[hh];
        int t = q0 + wid * 16 + g + hh * 8;
        size_t rowbase = (size_t)(b * T_ + t) * KP2_ + hd * 32;
        #pragma unroll
        for (int nf = 0; nf < 8; nf++) {
            uint32_t ph, pl;
            split2h(accO[nf][2*hh] * inv, accO[nf][2*hh+1] * inv, ph, pl);
            g_yp_h[rowbase + nf * 4 + tq] = ph;
            g_yp_l[rowbase + nf * 4 + tq] = pl;
        }
    }
}

// ---------------------------------------------------------------------------
extern "C" void kernel_launch(void* const* d_in, const int* in_sizes, int n_in,
                              void* d_out, int out_size)
{
    const float* x      = (const float*)d_in[0];
    const float* w_qkv  = (const float*)d_in[1];
    const float* w_proj = (const float*)d_in[2];
    const float* b_proj = (const float*)d_in[3];
    float* out = (float*)d_out;
    (void)in_sizes; (void)n_in; (void)out_size;

    cudaFuncSetAttribute(gemm_f16<0>,
                         cudaFuncAttributeMaxDynamicSharedMemorySize, GEMM_SMEM_BYTES);
    cudaFuncSetAttribute(gemm_f16<1>,
                         cudaFuncAttributeMaxDynamicSharedMemorySize, GEMM_SMEM_BYTES);
    cudaFuncSetAttribute(attn_mma,
                         cudaFuncAttributeMaxDynamicSharedMemorySize, ATTN_SMEM_B);

    rope_table_kernel<<<256, 256>>>();
    convert_x_kernel<<<M_ * K_ / 4 / 256, 256>>>(x);
    convert_w_kernel<0><<<(KP2_ * N3_ / 4) / 256, 256>>>(w_qkv, N3_);
    convert_w_kernel<1><<<(KP2_ * C_  / 4) / 256, 256>>>(w_proj, C_);
    gemm_f16<0><<<dim3(N3_ / 128, M_ / 128), 256, GEMM_SMEM_BYTES>>>(nullptr, nullptr);
    attn_mma<<<dim3(T_ / 64, BH_), 128, ATTN_SMEM_B>>>();
    gemm_f16<1><<<dim3(C_ / 128, M_ / 128), 256, GEMM_SMEM_BYTES>>>(b_proj, out);
}